// round 13
// baseline (speedup 1.0000x reference)
#include <cuda_runtime.h>
#include <cuda_fp16.h>
#include <math.h>
#include <stdint.h>

#define NN 169343
#define DIN 128
#define DH 256
#define DOUTF 40
#define EPSV 1e-5f
#define EMAX 2500000
#define NB_SCAN ((NN + 1023) / 1024)

// ---------------- scratch (static device globals) ----------------
__device__ __align__(128) float  g_dinv[NN];
__device__ __align__(128) float  g_selfn[NN];
__device__ __align__(128) int    g_cnt[NN];
__device__ __align__(128) int    g_cur[NN];
__device__ __align__(128) int    g_off[NN + 1];
__device__ __align__(128) int    g_blk[256];
__device__ __align__(128) int2   g_csr[EMAX];             // {src, bits(dinv[src])}
__device__ __align__(128) __half g_fa[(size_t)NN * DH];   // feature table (x / h1 / h2)
__device__ __align__(128) __half g_fz[(size_t)NN * DH];   // aggregated table (z1 / z2) + z3 fp16
// pre-split, pre-transposed, pre-paired weights: [Nc][K/2] u32 = {fp16(k), fp16(k+1)}
__device__ __align__(128) uint32_t g_w1h[DH * (DIN / 2)], g_w1l[DH * (DIN / 2)];
__device__ __align__(128) uint32_t g_w2h[DH * (DH / 2)],  g_w2l[DH * (DH / 2)];
__device__ __align__(128) uint32_t g_w3h[DOUTF * (DH / 2)], g_w3l[DOUTF * (DH / 2)];

// ---------------- CSR construction ----------------
__global__ void k_zero_int(int* __restrict__ p, int n) {
    int i = blockIdx.x * blockDim.x + threadIdx.x;
    if (i < n) p[i] = 0;
}
__global__ void k_count_int(const int* __restrict__ dst, int E, int* __restrict__ cnt) {
    int e = blockIdx.x * blockDim.x + threadIdx.x;
    if (e < E) atomicAdd(&cnt[dst[e]], 1);
}
__global__ __launch_bounds__(1024) void k_scan_block(const int* __restrict__ cnt,
                                                     int* __restrict__ off,
                                                     int* __restrict__ blk, int n) {
    __shared__ int s[1024];
    int t = threadIdx.x;
    int i = blockIdx.x * 1024 + t;
    int v = (i < n) ? cnt[i] : 0;
    s[t] = v;
    __syncthreads();
#pragma unroll
    for (int o = 1; o < 1024; o <<= 1) {
        int add = (t >= o) ? s[t - o] : 0;
        __syncthreads();
        s[t] += add;
        __syncthreads();
    }
    if (i <= n) off[i] = s[t] - v;
    if (t == 1023) blk[blockIdx.x] = s[1023];
}
// parallel exclusive scan of block sums (one 256-thread block, NB_SCAN <= 256)
__global__ __launch_bounds__(256) void k_scan_top(int* __restrict__ blk, int nb) {
    __shared__ int s[256];
    int t = threadIdx.x;
    int v = (t < nb) ? blk[t] : 0;
    s[t] = v;
    __syncthreads();
#pragma unroll
    for (int o = 1; o < 256; o <<= 1) {
        int add = (t >= o) ? s[t - o] : 0;
        __syncthreads();
        s[t] += add;
        __syncthreads();
    }
    if (t < nb) blk[t] = s[t] - v;  // exclusive
}
// fused: offset fixup + cur=0 + degree norms
__global__ void k_scan_add_norms(int* __restrict__ off, const int* __restrict__ blkv,
                                 const int* __restrict__ cnt, int* __restrict__ cur,
                                 float* __restrict__ dinv, float* __restrict__ selfn,
                                 int n, int E) {
    int i = blockIdx.x * blockDim.x + threadIdx.x;
    if (i < n) {
        off[i] += blkv[i / 1024];
        cur[i] = 0;
        float deg = (float)cnt[i] + 1.0f;
        dinv[i] = rsqrtf(deg);
        selfn[i] = 1.0f / deg;
    }
    if (i == 0) off[n] = E;
}
__global__ void k_fill(const int* __restrict__ src, const int* __restrict__ dst, int E,
                       const int* __restrict__ off, int* __restrict__ cur,
                       const float* __restrict__ dinv, int2* __restrict__ csr) {
    int e = blockIdx.x * blockDim.x + threadIdx.x;
    if (e >= E) return;
    int d = dst[e];
    int s = src[e];
    int pos = off[d] + atomicAdd(&cur[d], 1);
    csr[pos] = make_int2(s, __float_as_int(dinv[s]));
}

// ---------------- fp32 -> fp16 convert (x table) ----------------
__global__ void k_f32_to_f16(const float2* __restrict__ in, __half2* __restrict__ out, int n2) {
    int i = blockIdx.x * blockDim.x + threadIdx.x;
    if (i < n2) {
        float2 v = in[i];
        out[i] = __floats2half2_rn(v.x, v.y);
    }
}

// ---------------- weight split: W[K][Nc] fp32 -> Wp_h/Wp_l [Nc][K/2] u32 (paired fp16) ----------
__global__ void k_split_w(const float* __restrict__ W, uint32_t* __restrict__ Wh,
                          uint32_t* __restrict__ Wl, int K, int Nc) {
    int idx = blockIdx.x * blockDim.x + threadIdx.x;
    int Kp = K / 2;
    if (idx >= Nc * Kp) return;
    int n = idx / Kp;
    int kp = idx - n * Kp;
    float w0 = W[(size_t)(2 * kp) * Nc + n];
    float w1 = W[(size_t)(2 * kp + 1) * Nc + n];
    __half h0 = __float2half_rn(w0), h1 = __float2half_rn(w1);
    __half l0 = __float2half_rn(w0 - __half2float(h0));
    __half l1 = __float2half_rn(w1 - __half2float(h1));
    __half2 H = __halves2half2(h0, h1), L = __halves2half2(l0, l1);
    Wh[idx] = *(uint32_t*)&H;
    Wl[idx] = *(uint32_t*)&L;
}

// ---------------- warp-per-node CSR gather (fp16 in/out, fp32 accum), edge-unroll x4 ----------
template <int F>
__global__ __launch_bounds__(256) void k_gather_warp(
    const __half* __restrict__ feat, __half* __restrict__ aggout,
    const int* __restrict__ off, const int2* __restrict__ csr,
    const float* __restrict__ dinv, const float* __restrict__ selfn) {
    constexpr int VPL = F / 32;   // halves per lane (8 for 256, 4 for 128)
    constexpr int H2 = VPL / 2;   // half2 per lane
    int node = blockIdx.x * 8 + (threadIdx.x >> 5);
    int lane = threadIdx.x & 31;
    if (node >= NN) return;
    int beg = off[node], end = off[node + 1];

    float accx[H2], accy[H2];
#pragma unroll
    for (int i = 0; i < H2; i++) { accx[i] = 0.f; accy[i] = 0.f; }

    int e = beg;
    for (; e + 3 < end; e += 4) {
        int2 m0 = csr[e], m1 = csr[e + 1], m2 = csr[e + 2], m3 = csr[e + 3];
        float w0 = __int_as_float(m0.y), w1 = __int_as_float(m1.y);
        float w2 = __int_as_float(m2.y), w3 = __int_as_float(m3.y);
        uint32_t u0[H2], u1[H2], u2[H2], u3[H2];
        if (H2 == 4) {
            uint4 v0 = *(const uint4*)(feat + (size_t)m0.x * F + lane * VPL);
            uint4 v1 = *(const uint4*)(feat + (size_t)m1.x * F + lane * VPL);
            uint4 v2 = *(const uint4*)(feat + (size_t)m2.x * F + lane * VPL);
            uint4 v3 = *(const uint4*)(feat + (size_t)m3.x * F + lane * VPL);
            u0[0] = v0.x; u0[1] = v0.y; u0[2] = v0.z; u0[3] = v0.w;
            u1[0] = v1.x; u1[1] = v1.y; u1[2] = v1.z; u1[3] = v1.w;
            u2[0] = v2.x; u2[1] = v2.y; u2[2] = v2.z; u2[3] = v2.w;
            u3[0] = v3.x; u3[1] = v3.y; u3[2] = v3.z; u3[3] = v3.w;
        } else {
            uint2 v0 = *(const uint2*)(feat + (size_t)m0.x * F + lane * VPL);
            uint2 v1 = *(const uint2*)(feat + (size_t)m1.x * F + lane * VPL);
            uint2 v2 = *(const uint2*)(feat + (size_t)m2.x * F + lane * VPL);
            uint2 v3 = *(const uint2*)(feat + (size_t)m3.x * F + lane * VPL);
            u0[0] = v0.x; u0[1] = v0.y;
            u1[0] = v1.x; u1[1] = v1.y;
            u2[0] = v2.x; u2[1] = v2.y;
            u3[0] = v3.x; u3[1] = v3.y;
        }
#pragma unroll
        for (int i = 0; i < H2; i++) {
            float2 f0 = __half22float2(*(__half2*)&u0[i]);
            float2 f1 = __half22float2(*(__half2*)&u1[i]);
            float2 f2 = __half22float2(*(__half2*)&u2[i]);
            float2 f3 = __half22float2(*(__half2*)&u3[i]);
            accx[i] = fmaf(w0, f0.x, accx[i]); accy[i] = fmaf(w0, f0.y, accy[i]);
            accx[i] = fmaf(w1, f1.x, accx[i]); accy[i] = fmaf(w1, f1.y, accy[i]);
            accx[i] = fmaf(w2, f2.x, accx[i]); accy[i] = fmaf(w2, f2.y, accy[i]);
            accx[i] = fmaf(w3, f3.x, accx[i]); accy[i] = fmaf(w3, f3.y, accy[i]);
        }
    }
    for (; e < end; e++) {
        int2 m0 = csr[e];
        float w0 = __int_as_float(m0.y);
        uint32_t u0[H2];
        if (H2 == 4) {
            uint4 v0 = *(const uint4*)(feat + (size_t)m0.x * F + lane * VPL);
            u0[0] = v0.x; u0[1] = v0.y; u0[2] = v0.z; u0[3] = v0.w;
        } else {
            uint2 v0 = *(const uint2*)(feat + (size_t)m0.x * F + lane * VPL);
            u0[0] = v0.x; u0[1] = v0.y;
        }
#pragma unroll
        for (int i = 0; i < H2; i++) {
            float2 f0 = __half22float2(*(__half2*)&u0[i]);
            accx[i] = fmaf(w0, f0.x, accx[i]); accy[i] = fmaf(w0, f0.y, accy[i]);
        }
    }

    // self-loop term + store
    float di = dinv[node], sn = selfn[node];
    uint32_t us[H2], ou[H2];
    if (H2 == 4) {
        uint4 v = *(const uint4*)(feat + (size_t)node * F + lane * VPL);
        us[0] = v.x; us[1] = v.y; us[2] = v.z; us[3] = v.w;
    } else {
        uint2 v = *(const uint2*)(feat + (size_t)node * F + lane * VPL);
        us[0] = v.x; us[1] = v.y;
    }
#pragma unroll
    for (int i = 0; i < H2; i++) {
        float2 fs = __half22float2(*(__half2*)&us[i]);
        __half2 r = __floats2half2_rn(fmaf(di, accx[i], sn * fs.x),
                                      fmaf(di, accy[i], sn * fs.y));
        ou[i] = *(uint32_t*)&r;
    }
    if (H2 == 4) {
        *(uint4*)(aggout + (size_t)node * F + lane * VPL) = make_uint4(ou[0], ou[1], ou[2], ou[3]);
    } else {
        *(uint2*)(aggout + (size_t)node * F + lane * VPL) = make_uint2(ou[0], ou[1]);
    }
}

// ---------------- fused layer-3 gather (+bias) + log_softmax (fp16 z3) ----------------
__global__ __launch_bounds__(256) void k_gather40_softmax(
    const __half* __restrict__ z3, const float* __restrict__ b3,
    float* __restrict__ out,
    const int* __restrict__ off, const int2* __restrict__ csr,
    const float* __restrict__ dinv, const float* __restrict__ selfn) {
    int node = blockIdx.x * 8 + (threadIdx.x >> 5);
    int lane = threadIdx.x & 31;
    if (node >= NN) return;
    int beg = off[node], end = off[node + 1];
    float aa = 0.f, ab = 0.f;
    int e = beg;
    for (; e + 1 < end; e += 2) {
        int2 m0 = csr[e], m1 = csr[e + 1];
        float w0 = __int_as_float(m0.y), w1 = __int_as_float(m1.y);
        const __half* f0 = z3 + (size_t)m0.x * DOUTF;
        const __half* f1 = z3 + (size_t)m1.x * DOUTF;
        aa = fmaf(w0, __half2float(f0[lane]), aa);
        aa = fmaf(w1, __half2float(f1[lane]), aa);
        if (lane < 8) {
            ab = fmaf(w0, __half2float(f0[32 + lane]), ab);
            ab = fmaf(w1, __half2float(f1[32 + lane]), ab);
        }
    }
    if (e < end) {
        int2 m0 = csr[e];
        float w = __int_as_float(m0.y);
        const __half* fs = z3 + (size_t)m0.x * DOUTF;
        aa = fmaf(w, __half2float(fs[lane]), aa);
        if (lane < 8) ab = fmaf(w, __half2float(fs[32 + lane]), ab);
    }
    float di = dinv[node], sn = selfn[node];
    const __half* fz = z3 + (size_t)node * DOUTF;
    float a = fmaf(di, aa, fmaf(sn, __half2float(fz[lane]), b3[lane]));
    float b = (lane < 8)
        ? fmaf(di, ab, fmaf(sn, __half2float(fz[32 + lane]), b3[32 + lane]))
        : -3.402823e38f;
    float m = fmaxf(a, b);
#pragma unroll
    for (int o = 16; o; o >>= 1) m = fmaxf(m, __shfl_xor_sync(0xffffffffu, m, o));
    float s = expf(a - m) + ((lane < 8) ? expf(b - m) : 0.0f);
#pragma unroll
    for (int o = 16; o; o >>= 1) s += __shfl_xor_sync(0xffffffffu, s, o);
    float lse = m + logf(s);
    float* q = out + (size_t)node * DOUTF;
    q[lane] = a - lse;
    if (lane < 8) q[32 + lane] = b - lse;
}

// ---------------- fp16 MMA ----------------
__device__ __forceinline__ void mma_f16(float* c, const uint32_t* a, uint32_t b0, uint32_t b1) {
    asm volatile(
        "mma.sync.aligned.m16n8k16.row.col.f32.f16.f16.f32 "
        "{%0,%1,%2,%3}, {%4,%5,%6,%7}, {%8,%9}, {%0,%1,%2,%3};"
        : "+f"(c[0]), "+f"(c[1]), "+f"(c[2]), "+f"(c[3])
        : "r"(a[0]), "r"(a[1]), "r"(a[2]), "r"(a[3]), "r"(b0), "r"(b1));
}

// ---------------- tensor-core GEMM: A fp16, W split fp16 (2 MMAs/k16) ----------------
__global__ __launch_bounds__(256) void k_gemm_f16(
    const __half* __restrict__ A,
    const uint32_t* __restrict__ Bph, const uint32_t* __restrict__ Bpl,
    float* __restrict__ Cf32, __half* __restrict__ Cf16,
    int M, int K, int Nc,
    const float* __restrict__ bias,
    const float* __restrict__ gamma, const float* __restrict__ beta,
    const float* __restrict__ mean, const float* __restrict__ var,
    int bn_relu) {
    constexpr int BM = 128, BN = 64, BK = 32;
    constexpr int SP = 20;
    __shared__ uint32_t As[BM][SP];
    __shared__ uint32_t Bs_h[BN][SP], Bs_l[BN][SP];

    int tid = threadIdx.x;
    int lane = tid & 31;
    int wid = tid >> 5;
    int wm = (wid & 3) * 32;
    int wn = (wid >> 2) * 32;
    int row0 = blockIdx.y * BM;
    int col0 = blockIdx.x * BN;
    int g = lane >> 2;
    int tg = lane & 3;
    int Kp = K >> 1;

    float c[2][4][4];
#pragma unroll
    for (int mi = 0; mi < 2; mi++)
#pragma unroll
        for (int ni = 0; ni < 4; ni++)
#pragma unroll
            for (int r = 0; r < 4; r++) c[mi][ni][r] = 0.0f;

    for (int k0 = 0; k0 < K; k0 += BK) {
#pragma unroll
        for (int l = 0; l < 2; l++) {
            int idx = tid + l * 256;
            int m = idx >> 2;
            int q = idx & 3;
            int gr = row0 + m;
            uint4 v = make_uint4(0u, 0u, 0u, 0u);
            if (gr < M) v = *(const uint4*)(A + (size_t)gr * K + k0 + q * 8);
            As[m][q * 4 + 0] = v.x;
            As[m][q * 4 + 1] = v.y;
            As[m][q * 4 + 2] = v.z;
            As[m][q * 4 + 3] = v.w;
        }
#pragma unroll
        for (int l = 0; l < 4; l++) {
            int idx = tid + l * 256;
            int n = idx >> 4;
            int kp = idx & 15;
            int gc = col0 + n;
            uint32_t vh = 0u, vl = 0u;
            if (gc < Nc) {
                size_t o = (size_t)gc * Kp + (k0 >> 1) + kp;
                vh = Bph[o];
                vl = Bpl[o];
            }
            Bs_h[n][kp] = vh;
            Bs_l[n][kp] = vl;
        }
        __syncthreads();

#pragma unroll
        for (int ks = 0; ks < 2; ks++) {
            int kp0 = ks * 8;
            uint32_t a[2][4];
#pragma unroll
            for (int mi = 0; mi < 2; mi++) {
                int r = wm + mi * 16 + g;
                int cA = kp0 + tg;
                a[mi][0] = As[r][cA];
                a[mi][1] = As[r + 8][cA];
                a[mi][2] = As[r][cA + 4];
                a[mi][3] = As[r + 8][cA + 4];
            }
#pragma unroll
            for (int ni = 0; ni < 4; ni++) {
                int n = wn + ni * 8 + g;
                int cB = kp0 + tg;
                uint32_t bh0 = Bs_h[n][cB], bh1 = Bs_h[n][cB + 4];
                uint32_t bl0 = Bs_l[n][cB], bl1 = Bs_l[n][cB + 4];
#pragma unroll
                for (int mi = 0; mi < 2; mi++) {
                    mma_f16(c[mi][ni], a[mi], bh0, bh1);
                    mma_f16(c[mi][ni], a[mi], bl0, bl1);
                }
            }
        }
        __syncthreads();
    }

#pragma unroll
    for (int ni = 0; ni < 4; ni++) {
        int cc = col0 + wn + ni * 8 + 2 * tg;
        if (cc >= Nc) continue;
        float bb0 = bias ? bias[cc] : 0.0f;
        float bb1 = bias ? bias[cc + 1] : 0.0f;
        float sc0 = 1.0f, sh0 = 0.0f, sc1 = 1.0f, sh1 = 0.0f;
        if (bn_relu) {
            sc0 = rsqrtf(var[cc] + EPSV) * gamma[cc];
            sh0 = beta[cc] - mean[cc] * sc0;
            sc1 = rsqrtf(var[cc + 1] + EPSV) * gamma[cc + 1];
            sh1 = beta[cc + 1] - mean[cc + 1] * sc1;
        }
#pragma unroll
        for (int mi = 0; mi < 2; mi++) {
#pragma unroll
            for (int half = 0; half < 2; half++) {
                int r = row0 + wm + mi * 16 + g + half * 8;
                if (r >= M) continue;
                float v0 = c[mi][ni][half * 2 + 0] + bb0;
                float v1 = c[mi][ni][half * 2 + 1] + bb1;
                if (bn_relu) {
                    v0 = fmaxf(0.0f, fmaf(v0, sc0, sh0));
                    v1 = fmaxf(0.0f, fmaf(v1, sc1, sh1));
                }
                if (Cf32) *(float2*)&Cf32[(size_t)r * Nc + cc] = make_float2(v0, v1);
                if (Cf16) {
                    __half2 hv = __floats2half2_rn(v0, v1);
                    *(uint32_t*)&Cf16[(size_t)r * Nc + cc] = *(uint32_t*)&hv;
                }
            }
        }
    }
}

// ---------------- launch ----------------
static inline int cdiv(long long a, long long b) { return (int)((a + b - 1) / b); }

extern "C" void kernel_launch(void* const* d_in, const int* in_sizes, int n_in,
                              void* d_out, int out_size) {
    const float* x = (const float*)d_in[0];
    const int* ei = (const int*)d_in[1];
    const float* W1 = (const float*)d_in[2];
    const float* b1 = (const float*)d_in[3];
    const float* g1 = (const float*)d_in[4];
    const float* be1 = (const float*)d_in[5];
    const float* m1 = (const float*)d_in[6];
    const float* v1 = (const float*)d_in[7];
    const float* W2 = (const float*)d_in[8];
    const float* b2 = (const float*)d_in[9];
    const float* g2 = (const float*)d_in[10];
    const float* be2 = (const float*)d_in[11];
    const float* m2 = (const float*)d_in[12];
    const float* v2 = (const float*)d_in[13];
    const float* W3 = (const float*)d_in[14];
    const float* b3 = (const float*)d_in[15];
    const int E = in_sizes[1] / 2;
    const int* src = ei;
    const int* dst = ei + E;

    float* out = (float*)d_out;
    const bool have_emb = out_size >= NN * (DOUTF + DH);
    float* emb = out + (size_t)NN * DOUTF;

    float *dinv, *selfn;
    int *cnt, *cur, *off, *blk;
    int2* csr;
    __half *fa, *fz;
    uint32_t *w1h, *w1l, *w2h, *w2l, *w3h, *w3l;
    cudaGetSymbolAddress((void**)&dinv, g_dinv);
    cudaGetSymbolAddress((void**)&selfn, g_selfn);
    cudaGetSymbolAddress((void**)&cnt, g_cnt);
    cudaGetSymbolAddress((void**)&cur, g_cur);
    cudaGetSymbolAddress((void**)&off, g_off);
    cudaGetSymbolAddress((void**)&blk, g_blk);
    cudaGetSymbolAddress((void**)&csr, g_csr);
    cudaGetSymbolAddress((void**)&fa, g_fa);
    cudaGetSymbolAddress((void**)&fz, g_fz);
    cudaGetSymbolAddress((void**)&w1h, g_w1h);
    cudaGetSymbolAddress((void**)&w1l, g_w1l);
    cudaGetSymbolAddress((void**)&w2h, g_w2h);
    cudaGetSymbolAddress((void**)&w2l, g_w2l);
    cudaGetSymbolAddress((void**)&w3h, g_w3h);
    cudaGetSymbolAddress((void**)&w3l, g_w3l);

    const int T = 256;

    // ---- CSR build ----
    k_zero_int<<<cdiv(NN, T), T>>>(cnt, NN);
    k_count_int<<<cdiv(E, T), T>>>(dst, E, cnt);
    k_scan_block<<<NB_SCAN, 1024>>>(cnt, off, blk, NN);
    k_scan_top<<<1, 256>>>(blk, NB_SCAN);
    k_scan_add_norms<<<cdiv(NN, T), T>>>(off, blk, cnt, cur, dinv, selfn, NN, E);
    k_fill<<<cdiv(E, T), T>>>(src, dst, E, off, cur, dinv, csr);

    // ---- weight splits + x conversion ----
    k_split_w<<<cdiv(DH * (DIN / 2), T), T>>>(W1, w1h, w1l, DIN, DH);
    k_split_w<<<cdiv(DH * (DH / 2), T), T>>>(W2, w2h, w2l, DH, DH);
    k_split_w<<<cdiv(DOUTF * (DH / 2), T), T>>>(W3, w3h, w3l, DH, DOUTF);
    k_f32_to_f16<<<cdiv((long long)NN * DIN / 2, T), T>>>((const float2*)x, (__half2*)fa,
                                                          NN * DIN / 2);

    dim3 gridH((DH + 63) / 64, (NN + 127) / 128);
    dim3 gridO(1, (NN + 127) / 128);

    // ---- layer 1: z1 = Agg(x16); h1 = relu(bn1(z1@W1+b1)) -> fa (fp16) ----
    k_gather_warp<DIN><<<cdiv(NN, 8), 256>>>(fa, fz, off, csr, dinv, selfn);
    k_gemm_f16<<<gridH, 256>>>(fz, w1h, w1l, nullptr, fa, NN, DIN, DH, b1, g1, be1, m1, v1, 1);

    // ---- layer 2: z2 = Agg(h1); h2 = relu(bn2(z2@W2+b2)) -> emb fp32 + fa fp16 ----
    k_gather_warp<DH><<<cdiv(NN, 8), 256>>>(fa, fz, off, csr, dinv, selfn);
    k_gemm_f16<<<gridH, 256>>>(fz, w2h, w2l, have_emb ? emb : nullptr, fa,
                               NN, DH, DH, b2, g2, be2, m2, v2, 1);

    // ---- layer 3: z3 = h2@W3 (fp16 rows in fz); out = log_softmax(Agg(z3)+b3) ----
    k_gemm_f16<<<gridO, 256>>>(fa, w3h, w3l, nullptr, fz, NN, DH, DOUTF,
                               nullptr, nullptr, nullptr, nullptr, nullptr, 0);
    k_gather40_softmax<<<cdiv(NN, 8), 256>>>(fz, b3, out, off, csr, dinv, selfn);
}

// round 15
// speedup vs baseline: 1.0189x; 1.0189x over previous
#include <cuda_runtime.h>
#include <cuda_fp16.h>
#include <math.h>
#include <stdint.h>

#define NN 169343
#define DIN 128
#define DH 256
#define DOUTF 40
#define EPSV 1e-5f
#define EMAX 2500000
#define NB_SCAN ((NN + 1023) / 1024)

// ---------------- scratch (static device globals) ----------------
__device__ __align__(128) float  g_dinv[NN];
__device__ __align__(128) float  g_selfn[NN];
__device__ __align__(128) int    g_cnt[NN];
__device__ __align__(128) int    g_cur[NN];
__device__ __align__(128) int    g_off[NN + 1];
__device__ __align__(128) int    g_blk[256];
__device__ __align__(128) int2   g_csr[EMAX];             // {src, bits(dinv[src])}
__device__ __align__(128) __half g_fa[(size_t)NN * DH];   // feature table (x / h1 / h2)
__device__ __align__(128) __half g_fz[(size_t)NN * DH];   // aggregated table (z1 / z2) + z3 fp16
// pre-split, pre-transposed, pre-paired weights: [Nc][K/2] u32 = {fp16(k), fp16(k+1)}
__device__ __align__(128) uint32_t g_w1h[DH * (DIN / 2)], g_w1l[DH * (DIN / 2)];
__device__ __align__(128) uint32_t g_w2h[DH * (DH / 2)],  g_w2l[DH * (DH / 2)];
__device__ __align__(128) uint32_t g_w3h[DOUTF * (DH / 2)], g_w3l[DOUTF * (DH / 2)];

// ---------------- CSR construction ----------------
__global__ void k_zero_int(int* __restrict__ p, int n) {
    int i = blockIdx.x * blockDim.x + threadIdx.x;
    if (i < n) p[i] = 0;
}
__global__ void k_count_int(const int* __restrict__ dst, int E, int* __restrict__ cnt) {
    int e = blockIdx.x * blockDim.x + threadIdx.x;
    if (e < E) atomicAdd(&cnt[dst[e]], 1);
}
__global__ __launch_bounds__(1024) void k_scan_block(const int* __restrict__ cnt,
                                                     int* __restrict__ off,
                                                     int* __restrict__ blk, int n) {
    __shared__ int s[1024];
    int t = threadIdx.x;
    int i = blockIdx.x * 1024 + t;
    int v = (i < n) ? cnt[i] : 0;
    s[t] = v;
    __syncthreads();
#pragma unroll
    for (int o = 1; o < 1024; o <<= 1) {
        int add = (t >= o) ? s[t - o] : 0;
        __syncthreads();
        s[t] += add;
        __syncthreads();
    }
    if (i <= n) off[i] = s[t] - v;
    if (t == 1023) blk[blockIdx.x] = s[1023];
}
// parallel exclusive scan of block sums (one 256-thread block, NB_SCAN <= 256)
__global__ __launch_bounds__(256) void k_scan_top(int* __restrict__ blk, int nb) {
    __shared__ int s[256];
    int t = threadIdx.x;
    int v = (t < nb) ? blk[t] : 0;
    s[t] = v;
    __syncthreads();
#pragma unroll
    for (int o = 1; o < 256; o <<= 1) {
        int add = (t >= o) ? s[t - o] : 0;
        __syncthreads();
        s[t] += add;
        __syncthreads();
    }
    if (t < nb) blk[t] = s[t] - v;  // exclusive
}
// fused: offset fixup + cur=0 + degree norms
__global__ void k_scan_add_norms(int* __restrict__ off, const int* __restrict__ blkv,
                                 const int* __restrict__ cnt, int* __restrict__ cur,
                                 float* __restrict__ dinv, float* __restrict__ selfn,
                                 int n, int E) {
    int i = blockIdx.x * blockDim.x + threadIdx.x;
    if (i < n) {
        off[i] += blkv[i / 1024];
        cur[i] = 0;
        float deg = (float)cnt[i] + 1.0f;
        dinv[i] = rsqrtf(deg);
        selfn[i] = 1.0f / deg;
    }
    if (i == 0) off[n] = E;
}
__global__ void k_fill(const int* __restrict__ src, const int* __restrict__ dst, int E,
                       const int* __restrict__ off, int* __restrict__ cur,
                       const float* __restrict__ dinv, int2* __restrict__ csr) {
    int e = blockIdx.x * blockDim.x + threadIdx.x;
    if (e >= E) return;
    int d = dst[e];
    int s = src[e];
    int pos = off[d] + atomicAdd(&cur[d], 1);
    csr[pos] = make_int2(s, __float_as_int(dinv[s]));
}

// ---------------- fp32 -> fp16 convert (x table) ----------------
__global__ void k_f32_to_f16(const float2* __restrict__ in, __half2* __restrict__ out, int n2) {
    int i = blockIdx.x * blockDim.x + threadIdx.x;
    if (i < n2) {
        float2 v = in[i];
        out[i] = __floats2half2_rn(v.x, v.y);
    }
}

// ---------------- weight split: W[K][Nc] fp32 -> Wp_h/Wp_l [Nc][K/2] u32 (paired fp16) ----------
__global__ void k_split_w(const float* __restrict__ W, uint32_t* __restrict__ Wh,
                          uint32_t* __restrict__ Wl, int K, int Nc) {
    int idx = blockIdx.x * blockDim.x + threadIdx.x;
    int Kp = K / 2;
    if (idx >= Nc * Kp) return;
    int n = idx / Kp;
    int kp = idx - n * Kp;
    float w0 = W[(size_t)(2 * kp) * Nc + n];
    float w1 = W[(size_t)(2 * kp + 1) * Nc + n];
    __half h0 = __float2half_rn(w0), h1 = __float2half_rn(w1);
    __half l0 = __float2half_rn(w0 - __half2float(h0));
    __half l1 = __float2half_rn(w1 - __half2float(h1));
    __half2 H = __halves2half2(h0, h1), L = __halves2half2(l0, l1);
    Wh[idx] = *(uint32_t*)&H;
    Wl[idx] = *(uint32_t*)&L;
}

// ---------------- warp-per-node CSR gather (fp16 in/out, fp32 accum), edge-unroll x2 ----------
template <int F>
__global__ __launch_bounds__(256) void k_gather_warp(
    const __half* __restrict__ feat, __half* __restrict__ aggout,
    const int* __restrict__ off, const int2* __restrict__ csr,
    const float* __restrict__ dinv, const float* __restrict__ selfn) {
    constexpr int VPL = F / 32;   // halves per lane (8 for 256, 4 for 128)
    constexpr int H2 = VPL / 2;   // half2 per lane
    int node = blockIdx.x * 8 + (threadIdx.x >> 5);
    int lane = threadIdx.x & 31;
    if (node >= NN) return;
    int beg = off[node], end = off[node + 1];

    float accx[H2], accy[H2];
#pragma unroll
    for (int i = 0; i < H2; i++) { accx[i] = 0.f; accy[i] = 0.f; }

    int e = beg;
    for (; e + 1 < end; e += 2) {
        int2 m0 = csr[e], m1 = csr[e + 1];
        float w0 = __int_as_float(m0.y), w1 = __int_as_float(m1.y);
        uint32_t u0[H2], u1[H2];
        if (H2 == 4) {
            uint4 v0 = *(const uint4*)(feat + (size_t)m0.x * F + lane * VPL);
            uint4 v1 = *(const uint4*)(feat + (size_t)m1.x * F + lane * VPL);
            u0[0] = v0.x; u0[1] = v0.y; u0[2] = v0.z; u0[3] = v0.w;
            u1[0] = v1.x; u1[1] = v1.y; u1[2] = v1.z; u1[3] = v1.w;
        } else {
            uint2 v0 = *(const uint2*)(feat + (size_t)m0.x * F + lane * VPL);
            uint2 v1 = *(const uint2*)(feat + (size_t)m1.x * F + lane * VPL);
            u0[0] = v0.x; u0[1] = v0.y;
            u1[0] = v1.x; u1[1] = v1.y;
        }
#pragma unroll
        for (int i = 0; i < H2; i++) {
            float2 f0 = __half22float2(*(__half2*)&u0[i]);
            float2 f1 = __half22float2(*(__half2*)&u1[i]);
            accx[i] = fmaf(w0, f0.x, accx[i]); accy[i] = fmaf(w0, f0.y, accy[i]);
            accx[i] = fmaf(w1, f1.x, accx[i]); accy[i] = fmaf(w1, f1.y, accy[i]);
        }
    }
    if (e < end) {
        int2 m0 = csr[e];
        float w0 = __int_as_float(m0.y);
        uint32_t u0[H2];
        if (H2 == 4) {
            uint4 v0 = *(const uint4*)(feat + (size_t)m0.x * F + lane * VPL);
            u0[0] = v0.x; u0[1] = v0.y; u0[2] = v0.z; u0[3] = v0.w;
        } else {
            uint2 v0 = *(const uint2*)(feat + (size_t)m0.x * F + lane * VPL);
            u0[0] = v0.x; u0[1] = v0.y;
        }
#pragma unroll
        for (int i = 0; i < H2; i++) {
            float2 f0 = __half22float2(*(__half2*)&u0[i]);
            accx[i] = fmaf(w0, f0.x, accx[i]); accy[i] = fmaf(w0, f0.y, accy[i]);
        }
    }

    // self-loop term + store
    float di = dinv[node], sn = selfn[node];
    uint32_t us[H2], ou[H2];
    if (H2 == 4) {
        uint4 v = *(const uint4*)(feat + (size_t)node * F + lane * VPL);
        us[0] = v.x; us[1] = v.y; us[2] = v.z; us[3] = v.w;
    } else {
        uint2 v = *(const uint2*)(feat + (size_t)node * F + lane * VPL);
        us[0] = v.x; us[1] = v.y;
    }
#pragma unroll
    for (int i = 0; i < H2; i++) {
        float2 fs = __half22float2(*(__half2*)&us[i]);
        __half2 r = __floats2half2_rn(fmaf(di, accx[i], sn * fs.x),
                                      fmaf(di, accy[i], sn * fs.y));
        ou[i] = *(uint32_t*)&r;
    }
    if (H2 == 4) {
        *(uint4*)(aggout + (size_t)node * F + lane * VPL) = make_uint4(ou[0], ou[1], ou[2], ou[3]);
    } else {
        *(uint2*)(aggout + (size_t)node * F + lane * VPL) = make_uint2(ou[0], ou[1]);
    }
}

// ---------------- fused layer-3 gather (+bias) + log_softmax (fp16 z3) ----------------
__global__ __launch_bounds__(256) void k_gather40_softmax(
    const __half* __restrict__ z3, const float* __restrict__ b3,
    float* __restrict__ out,
    const int* __restrict__ off, const int2* __restrict__ csr,
    const float* __restrict__ dinv, const float* __restrict__ selfn) {
    int node = blockIdx.x * 8 + (threadIdx.x >> 5);
    int lane = threadIdx.x & 31;
    if (node >= NN) return;
    int beg = off[node], end = off[node + 1];
    float aa = 0.f, ab = 0.f;
    int e = beg;
    for (; e + 1 < end; e += 2) {
        int2 m0 = csr[e], m1 = csr[e + 1];
        float w0 = __int_as_float(m0.y), w1 = __int_as_float(m1.y);
        const __half* f0 = z3 + (size_t)m0.x * DOUTF;
        const __half* f1 = z3 + (size_t)m1.x * DOUTF;
        aa = fmaf(w0, __half2float(f0[lane]), aa);
        aa = fmaf(w1, __half2float(f1[lane]), aa);
        if (lane < 8) {
            ab = fmaf(w0, __half2float(f0[32 + lane]), ab);
            ab = fmaf(w1, __half2float(f1[32 + lane]), ab);
        }
    }
    if (e < end) {
        int2 m0 = csr[e];
        float w = __int_as_float(m0.y);
        const __half* fs = z3 + (size_t)m0.x * DOUTF;
        aa = fmaf(w, __half2float(fs[lane]), aa);
        if (lane < 8) ab = fmaf(w, __half2float(fs[32 + lane]), ab);
    }
    float di = dinv[node], sn = selfn[node];
    const __half* fz = z3 + (size_t)node * DOUTF;
    float a = fmaf(di, aa, fmaf(sn, __half2float(fz[lane]), b3[lane]));
    float b = (lane < 8)
        ? fmaf(di, ab, fmaf(sn, __half2float(fz[32 + lane]), b3[32 + lane]))
        : -3.402823e38f;
    float m = fmaxf(a, b);
#pragma unroll
    for (int o = 16; o; o >>= 1) m = fmaxf(m, __shfl_xor_sync(0xffffffffu, m, o));
    float s = expf(a - m) + ((lane < 8) ? expf(b - m) : 0.0f);
#pragma unroll
    for (int o = 16; o; o >>= 1) s += __shfl_xor_sync(0xffffffffu, s, o);
    float lse = m + logf(s);
    float* q = out + (size_t)node * DOUTF;
    q[lane] = a - lse;
    if (lane < 8) q[32 + lane] = b - lse;
}

// ---------------- fp16 MMA ----------------
__device__ __forceinline__ void mma_f16(float* c, const uint32_t* a, uint32_t b0, uint32_t b1) {
    asm volatile(
        "mma.sync.aligned.m16n8k16.row.col.f32.f16.f16.f32 "
        "{%0,%1,%2,%3}, {%4,%5,%6,%7}, {%8,%9}, {%0,%1,%2,%3};"
        : "+f"(c[0]), "+f"(c[1]), "+f"(c[2]), "+f"(c[3])
        : "r"(a[0]), "r"(a[1]), "r"(a[2]), "r"(a[3]), "r"(b0), "r"(b1));
}

// ---------------- tensor-core GEMM: A fp16, W split fp16 (2 MMAs/k16) ----------------
__global__ __launch_bounds__(256) void k_gemm_f16(
    const __half* __restrict__ A,
    const uint32_t* __restrict__ Bph, const uint32_t* __restrict__ Bpl,
    float* __restrict__ Cf32, __half* __restrict__ Cf16,
    int M, int K, int Nc,
    const float* __restrict__ bias,
    const float* __restrict__ gamma, const float* __restrict__ beta,
    const float* __restrict__ mean, const float* __restrict__ var,
    int bn_relu) {
    constexpr int BM = 128, BN = 64, BK = 32;
    constexpr int SP = 20;
    __shared__ uint32_t As[BM][SP];
    __shared__ uint32_t Bs_h[BN][SP], Bs_l[BN][SP];

    int tid = threadIdx.x;
    int lane = tid & 31;
    int wid = tid >> 5;
    int wm = (wid & 3) * 32;
    int wn = (wid >> 2) * 32;
    int row0 = blockIdx.y * BM;
    int col0 = blockIdx.x * BN;
    int g = lane >> 2;
    int tg = lane & 3;
    int Kp = K >> 1;

    float c[2][4][4];
#pragma unroll
    for (int mi = 0; mi < 2; mi++)
#pragma unroll
        for (int ni = 0; ni < 4; ni++)
#pragma unroll
            for (int r = 0; r < 4; r++) c[mi][ni][r] = 0.0f;

    for (int k0 = 0; k0 < K; k0 += BK) {
#pragma unroll
        for (int l = 0; l < 2; l++) {
            int idx = tid + l * 256;
            int m = idx >> 2;
            int q = idx & 3;
            int gr = row0 + m;
            uint4 v = make_uint4(0u, 0u, 0u, 0u);
            if (gr < M) v = *(const uint4*)(A + (size_t)gr * K + k0 + q * 8);
            As[m][q * 4 + 0] = v.x;
            As[m][q * 4 + 1] = v.y;
            As[m][q * 4 + 2] = v.z;
            As[m][q * 4 + 3] = v.w;
        }
#pragma unroll
        for (int l = 0; l < 4; l++) {
            int idx = tid + l * 256;
            int n = idx >> 4;
            int kp = idx & 15;
            int gc = col0 + n;
            uint32_t vh = 0u, vl = 0u;
            if (gc < Nc) {
                size_t o = (size_t)gc * Kp + (k0 >> 1) + kp;
                vh = Bph[o];
                vl = Bpl[o];
            }
            Bs_h[n][kp] = vh;
            Bs_l[n][kp] = vl;
        }
        __syncthreads();

#pragma unroll
        for (int ks = 0; ks < 2; ks++) {
            int kp0 = ks * 8;
            uint32_t a[2][4];
#pragma unroll
            for (int mi = 0; mi < 2; mi++) {
                int r = wm + mi * 16 + g;
                int cA = kp0 + tg;
                a[mi][0] = As[r][cA];
                a[mi][1] = As[r + 8][cA];
                a[mi][2] = As[r][cA + 4];
                a[mi][3] = As[r + 8][cA + 4];
            }
#pragma unroll
            for (int ni = 0; ni < 4; ni++) {
                int n = wn + ni * 8 + g;
                int cB = kp0 + tg;
                uint32_t bh0 = Bs_h[n][cB], bh1 = Bs_h[n][cB + 4];
                uint32_t bl0 = Bs_l[n][cB], bl1 = Bs_l[n][cB + 4];
#pragma unroll
                for (int mi = 0; mi < 2; mi++) {
                    mma_f16(c[mi][ni], a[mi], bh0, bh1);
                    mma_f16(c[mi][ni], a[mi], bl0, bl1);
                }
            }
        }
        __syncthreads();
    }

#pragma unroll
    for (int ni = 0; ni < 4; ni++) {
        int cc = col0 + wn + ni * 8 + 2 * tg;
        if (cc >= Nc) continue;
        float bb0 = bias ? bias[cc] : 0.0f;
        float bb1 = bias ? bias[cc + 1] : 0.0f;
        float sc0 = 1.0f, sh0 = 0.0f, sc1 = 1.0f, sh1 = 0.0f;
        if (bn_relu) {
            sc0 = rsqrtf(var[cc] + EPSV) * gamma[cc];
            sh0 = beta[cc] - mean[cc] * sc0;
            sc1 = rsqrtf(var[cc + 1] + EPSV) * gamma[cc + 1];
            sh1 = beta[cc + 1] - mean[cc + 1] * sc1;
        }
#pragma unroll
        for (int mi = 0; mi < 2; mi++) {
#pragma unroll
            for (int half = 0; half < 2; half++) {
                int r = row0 + wm + mi * 16 + g + half * 8;
                if (r >= M) continue;
                float v0 = c[mi][ni][half * 2 + 0] + bb0;
                float v1 = c[mi][ni][half * 2 + 1] + bb1;
                if (bn_relu) {
                    v0 = fmaxf(0.0f, fmaf(v0, sc0, sh0));
                    v1 = fmaxf(0.0f, fmaf(v1, sc1, sh1));
                }
                if (Cf32) *(float2*)&Cf32[(size_t)r * Nc + cc] = make_float2(v0, v1);
                if (Cf16) {
                    __half2 hv = __floats2half2_rn(v0, v1);
                    *(uint32_t*)&Cf16[(size_t)r * Nc + cc] = *(uint32_t*)&hv;
                }
            }
        }
    }
}

// ---------------- launch ----------------
static inline int cdiv(long long a, long long b) { return (int)((a + b - 1) / b); }

extern "C" void kernel_launch(void* const* d_in, const int* in_sizes, int n_in,
                              void* d_out, int out_size) {
    const float* x = (const float*)d_in[0];
    const int* ei = (const int*)d_in[1];
    const float* W1 = (const float*)d_in[2];
    const float* b1 = (const float*)d_in[3];
    const float* g1 = (const float*)d_in[4];
    const float* be1 = (const float*)d_in[5];
    const float* m1 = (const float*)d_in[6];
    const float* v1 = (const float*)d_in[7];
    const float* W2 = (const float*)d_in[8];
    const float* b2 = (const float*)d_in[9];
    const float* g2 = (const float*)d_in[10];
    const float* be2 = (const float*)d_in[11];
    const float* m2 = (const float*)d_in[12];
    const float* v2 = (const float*)d_in[13];
    const float* W3 = (const float*)d_in[14];
    const float* b3 = (const float*)d_in[15];
    const int E = in_sizes[1] / 2;
    const int* src = ei;
    const int* dst = ei + E;

    float* out = (float*)d_out;
    const bool have_emb = out_size >= NN * (DOUTF + DH);
    float* emb = out + (size_t)NN * DOUTF;

    float *dinv, *selfn;
    int *cnt, *cur, *off, *blk;
    int2* csr;
    __half *fa, *fz;
    uint32_t *w1h, *w1l, *w2h, *w2l, *w3h, *w3l;
    cudaGetSymbolAddress((void**)&dinv, g_dinv);
    cudaGetSymbolAddress((void**)&selfn, g_selfn);
    cudaGetSymbolAddress((void**)&cnt, g_cnt);
    cudaGetSymbolAddress((void**)&cur, g_cur);
    cudaGetSymbolAddress((void**)&off, g_off);
    cudaGetSymbolAddress((void**)&blk, g_blk);
    cudaGetSymbolAddress((void**)&csr, g_csr);
    cudaGetSymbolAddress((void**)&fa, g_fa);
    cudaGetSymbolAddress((void**)&fz, g_fz);
    cudaGetSymbolAddress((void**)&w1h, g_w1h);
    cudaGetSymbolAddress((void**)&w1l, g_w1l);
    cudaGetSymbolAddress((void**)&w2h, g_w2h);
    cudaGetSymbolAddress((void**)&w2l, g_w2l);
    cudaGetSymbolAddress((void**)&w3h, g_w3h);
    cudaGetSymbolAddress((void**)&w3l, g_w3l);

    const int T = 256;

    // ---- CSR build ----
    k_zero_int<<<cdiv(NN, T), T>>>(cnt, NN);
    k_count_int<<<cdiv(E, T), T>>>(dst, E, cnt);
    k_scan_block<<<NB_SCAN, 1024>>>(cnt, off, blk, NN);
    k_scan_top<<<1, 256>>>(blk, NB_SCAN);
    k_scan_add_norms<<<cdiv(NN, T), T>>>(off, blk, cnt, cur, dinv, selfn, NN, E);
    k_fill<<<cdiv(E, T), T>>>(src, dst, E, off, cur, dinv, csr);

    // ---- weight splits + x conversion ----
    k_split_w<<<cdiv(DH * (DIN / 2), T), T>>>(W1, w1h, w1l, DIN, DH);
    k_split_w<<<cdiv(DH * (DH / 2), T), T>>>(W2, w2h, w2l, DH, DH);
    k_split_w<<<cdiv(DOUTF * (DH / 2), T), T>>>(W3, w3h, w3l, DH, DOUTF);
    k_f32_to_f16<<<cdiv((long long)NN * DIN / 2, T), T>>>((const float2*)x, (__half2*)fa,
                                                          NN * DIN / 2);

    dim3 gridH((DH + 63) / 64, (NN + 127) / 128);
    dim3 gridO(1, (NN + 127) / 128);

    // ---- layer 1: z1 = Agg(x16); h1 = relu(bn1(z1@W1+b1)) -> fa (fp16) ----
    k_gather_warp<DIN><<<cdiv(NN, 8), 256>>>(fa, fz, off, csr, dinv, selfn);
    k_gemm_f16<<<gridH, 256>>>(fz, w1h, w1l, nullptr, fa, NN, DIN, DH, b1, g1, be1, m1, v1, 1);

    // ---- layer 2: z2 = Agg(h1); h2 = relu(bn2(z2@W2+b2)) -> emb fp32 + fa fp16 ----
    k_gather_warp<DH><<<cdiv(NN, 8), 256>>>(fa, fz, off, csr, dinv, selfn);
    k_gemm_f16<<<gridH, 256>>>(fz, w2h, w2l, have_emb ? emb : nullptr, fa,
                               NN, DH, DH, b2, g2, be2, m2, v2, 1);

    // ---- layer 3: z3 = h2@W3 (fp16 rows in fz); out = log_softmax(Agg(z3)+b3) ----
    k_gemm_f16<<<gridO, 256>>>(fa, w3h, w3l, nullptr, fz, NN, DH, DOUTF,
                               nullptr, nullptr, nullptr, nullptr, nullptr, 0);
    k_gather40_softmax<<<cdiv(NN, 8), 256>>>(fz, b3, out, off, csr, dinv, selfn);
}